// round 17
// baseline (speedup 1.0000x reference)
#include <cuda_runtime.h>
#include <cuda_fp16.h>
#include <math.h>
#include <stdint.h>
#include <stddef.h>

#define B_   2
#define S_   2048
#define HID_ 2048
#define H_   16
#define HS_  128
#define RD_  32

// ---------------- scratch (device globals) ----------------
__device__ __half g_qkv[(size_t)B_ * S_ * 3 * HID_];   // fp16 now

__device__ __half g_A[(size_t)B_ * S_ * HID_];
__device__ __half g_Wq[(size_t)HID_ * 3 * HID_];
__device__ __half g_Wd[(size_t)HID_ * HID_];
__device__ __half g_Att[(size_t)B_ * S_ * HID_];

__device__ __half g_Q[(size_t)B_ * H_ * S_ * HS_];
__device__ __half g_Kt[(size_t)B_ * H_ * HS_ * S_];
__device__ __half g_V[(size_t)B_ * H_ * S_ * HS_];

// ---------------- PTX helpers ----------------
__device__ __forceinline__ unsigned smem_u32(const void* p) {
    return (unsigned)__cvta_generic_to_shared(p);
}
__device__ __forceinline__ void cp16(unsigned s, const void* g) {
    asm volatile("cp.async.cg.shared.global [%0], [%1], 16;" :: "r"(s), "l"(g));
}
__device__ __forceinline__ void cp_commit() {
    asm volatile("cp.async.commit_group;");
}
__device__ __forceinline__ void cp_wait_1() {
    asm volatile("cp.async.wait_group 1;");
}
__device__ __forceinline__ void cp_wait_0() {
    asm volatile("cp.async.wait_group 0;");
}
__device__ __forceinline__ void ldm4(unsigned* r, unsigned a) {
    asm volatile("ldmatrix.sync.aligned.m8n8.x4.shared.b16 {%0,%1,%2,%3}, [%4];"
        : "=r"(r[0]), "=r"(r[1]), "=r"(r[2]), "=r"(r[3]) : "r"(a));
}
__device__ __forceinline__ void ldm4t(unsigned* r, unsigned a) {
    asm volatile("ldmatrix.sync.aligned.m8n8.x4.trans.shared.b16 {%0,%1,%2,%3}, [%4];"
        : "=r"(r[0]), "=r"(r[1]), "=r"(r[2]), "=r"(r[3]) : "r"(a));
}
__device__ __forceinline__ void mma16816(float* d, const unsigned* a, const unsigned* b) {
    asm volatile(
        "mma.sync.aligned.m16n8k16.row.col.f32.f16.f16.f32 "
        "{%0,%1,%2,%3},{%4,%5,%6,%7},{%8,%9},{%0,%1,%2,%3};"
        : "+f"(d[0]), "+f"(d[1]), "+f"(d[2]), "+f"(d[3])
        : "r"(a[0]), "r"(a[1]), "r"(a[2]), "r"(a[3]), "r"(b[0]), "r"(b[1]));
}

// ---------------- fp16 conversion ----------------
__global__ __launch_bounds__(256) void split1_fp16(
    const float* __restrict__ x, __half* __restrict__ out, int n4)
{
    int i = blockIdx.x * 256 + threadIdx.x;
    if (i >= n4) return;
    float4 v = ((const float4*)x)[i];
    ((__half2*)out)[i * 2 + 0] = __floats2half2_rn(v.x, v.y);
    ((__half2*)out)[i * 2 + 1] = __floats2half2_rn(v.z, v.w);
}

// ================= fp16 GEMM, block 128x256, BK=64, warp tile 64x64 =================
#define GBM 128
#define GBN 256
#define GBK 64
#define GA_STRIDE 72                               // 64 + 8 pad
#define GB_STRIDE 264                              // 256 + 8 pad
#define GA_BYTES (128 * GA_STRIDE * 2)             // 18432
#define GB_BYTES (64 * GB_STRIDE * 2)              // 33792
#define GSTAGE   (GA_BYTES + GB_BYTES)             // 52224
#define GEMM_SMEM (2 * GSTAGE)                     // 104448

__device__ __forceinline__ void gemm_load_stage(
    unsigned base, int t,
    const __half* __restrict__ As, const __half* __restrict__ Bs,
    int brow, int bcol, int k0, int K, int N)
{
    unsigned aS = base;
    unsigned bS = base + GA_BYTES;
#pragma unroll
    for (int i = 0; i < 4; i++) {                  // A: 128 x 64
        int c = t + i * 256;
        int ar = c >> 3;
        int ak = (c & 7) * 8;
        size_t ga = (size_t)(brow + ar) * K + k0 + ak;
        cp16(aS + (unsigned)(ar * GA_STRIDE + ak) * 2u, As + ga);
    }
#pragma unroll
    for (int i = 0; i < 8; i++) {                  // B: 64 x 256
        int c = t + i * 256;
        int br = c >> 5;
        int nn = (c & 31) * 8;
        size_t gb = (size_t)(k0 + br) * N + bcol + nn;
        cp16(bS + (unsigned)(br * GB_STRIDE + nn) * 2u, Bs + gb);
    }
    cp_commit();
}

__device__ __forceinline__ void gemm_compute_stage(
    unsigned base, int lane, int wm, int wn, float acc[4][8][4])
{
    unsigned aS = base;
    unsigned bS = base + GA_BYTES;
#pragma unroll
    for (int kk = 0; kk < 64; kk += 16) {
        unsigned ah[4][4];
        const int arow = wm * 64 + (lane & 15);
        const int akc = kk + ((lane >> 4) << 3);
#pragma unroll
        for (int mt = 0; mt < 4; mt++)
            ldm4(ah[mt], aS + (unsigned)((arow + mt * 16) * GA_STRIDE + akc) * 2u);
        const int krow = kk + (lane & 15);
        const int nc0 = wn * 64 + ((lane >> 4) << 3);
#pragma unroll
        for (int nb = 0; nb < 4; nb++) {
            unsigned bh[4];
            ldm4t(bh, bS + (unsigned)(krow * GB_STRIDE + nc0 + nb * 16) * 2u);
#pragma unroll
            for (int mt = 0; mt < 4; mt++)
#pragma unroll
                for (int hf = 0; hf < 2; hf++)
                    mma16816(acc[mt][nb * 2 + hf], ah[mt], &bh[hf * 2]);
        }
    }
}

template <int OUT16>
__global__ __launch_bounds__(256, 1) void gemm_big(
    const __half* __restrict__ As, const __half* __restrict__ Bs,
    const float* __restrict__ bias, void* __restrict__ Cv,
    int M, int N, int K)
{
    extern __shared__ char dynsm[];
    const int t = threadIdx.x;
    const int lane = t & 31;
    const int warp = t >> 5;
    const int wm = warp >> 2;       // 0..1
    const int wn = warp & 3;        // 0..3
    const int brow = blockIdx.y * GBM;
    const int bcol = blockIdx.x * GBN;

    const unsigned smbase = smem_u32(dynsm);

    float acc[4][8][4];
#pragma unroll
    for (int i = 0; i < 4; i++)
#pragma unroll
        for (int j = 0; j < 8; j++)
#pragma unroll
            for (int k = 0; k < 4; k++) acc[i][j][k] = 0.f;

    const int niter = K / GBK;
    gemm_load_stage(smbase, t, As, Bs, brow, bcol, 0, K, N);
    for (int it = 0; it < niter; it++) {
        if (it + 1 < niter) {
            gemm_load_stage(smbase + ((it + 1) & 1) * GSTAGE, t,
                            As, Bs, brow, bcol, (it + 1) * GBK, K, N);
            cp_wait_1();
        } else {
            cp_wait_0();
        }
        __syncthreads();
        gemm_compute_stage(smbase + (it & 1) * GSTAGE, lane, wm, wn, acc);
        __syncthreads();
    }

    const int g = lane >> 2;
    const int t2 = (lane & 3) * 2;
#pragma unroll
    for (int mt = 0; mt < 4; mt++) {
        int row = brow + wm * 64 + mt * 16 + g;
#pragma unroll
        for (int nt = 0; nt < 8; nt++) {
            int col = bcol + wn * 64 + nt * 8 + t2;
            float b0 = bias[col], b1 = bias[col + 1];
            float v0 = acc[mt][nt][0] + b0, v1 = acc[mt][nt][1] + b1;
            float v2 = acc[mt][nt][2] + b0, v3 = acc[mt][nt][3] + b1;
            if (OUT16) {
                __half* C = (__half*)Cv;
                *(__half2*)(C + (size_t)row * N + col)       = __floats2half2_rn(v0, v1);
                *(__half2*)(C + (size_t)(row + 8) * N + col) = __floats2half2_rn(v2, v3);
            } else {
                float* C = (float*)Cv;
                *(float2*)(C + (size_t)row * N + col)       = make_float2(v0, v1);
                *(float2*)(C + (size_t)(row + 8) * N + col) = make_float2(v2, v3);
            }
        }
    }
}

// ---------------- rotary (fp16 qkv in) + scatter (Q,V natural; K transposed) ----------------
#define ROT_SMEM (128 * 133 * 4)

__global__ __launch_bounds__(256) void rotary_split(
    const __half* __restrict__ qkv, const int* __restrict__ pos,
    __half* __restrict__ Q, __half* __restrict__ Kt, __half* __restrict__ V)
{
    extern __shared__ char dynsm[];
    unsigned* ksm = (unsigned*)dynsm;

    const int t = threadIdx.x;
    const int s0 = blockIdx.x * 128;
    const int h = blockIdx.y, b = blockIdx.z;

#pragma unroll 4
    for (int i = 0; i < 64; i++) {
        int idx = t + i * 256;
        int d = idx & 127;
        int s = idx >> 7;
        const __half* base = qkv + (size_t)(b * S_ + s0 + s) * (3 * HID_) + h * (3 * HS_);
        float q = __half2float(base[d]);
        float k = __half2float(base[HS_ + d]);
        __half v = base[2 * HS_ + d];

        if (d < RD_) {
            float p = (float)pos[b * S_ + s0 + s];
            int fi = d & 15;
            float f = p * expf((float)(2 * fi) * (-1.0f / (float)RD_) * 9.210340371976184f);
            float c = cosf(f);
            float sn = sinf(f);
            int pd = (d < 16) ? d + 16 : d - 16;
            float sgn = (d < 16) ? -1.f : 1.f;
            float qp = __half2float(base[pd]);
            float kp = __half2float(base[HS_ + pd]);
            q = q * c + sgn * qp * sn;
            k = k * c + sgn * kp * sn;
        }

        size_t oi = ((size_t)(b * H_ + h) * S_ + s0 + s) * HS_ + d;
        Q[oi] = __float2half_rn(q);
        V[oi] = v;

        ksm[s * 133 + d] = (unsigned)__half_as_ushort(__float2half_rn(k));
    }
    __syncthreads();

#pragma unroll 4
    for (int i = 0; i < 64; i++) {
        int idx = t + i * 256;
        int s = idx & 127;
        int d = idx >> 7;
        unsigned pk = ksm[s * 133 + d];
        size_t ko = ((size_t)(b * H_ + h) * HS_ + d) * S_ + s0 + s;
        Kt[ko] = __ushort_as_half((unsigned short)(pk & 0xffffu));
    }
}

// ---------------- tensor-core flash attention (causal; fp16 single-pass) ----------------
#define FQ_STRIDE 136
#define FK_STRIDE 72
#define FV_STRIDE 136
#define FQ_BYTES (128 * FQ_STRIDE * 2)
#define FK_BYTES (128 * FK_STRIDE * 2)
#define FV_BYTES (64 * FV_STRIDE * 2)
#define FSTAGE   (FK_BYTES + FV_BYTES)
#define FA_SMEM  (FQ_BYTES + 2 * FSTAGE)

__device__ __forceinline__ void fa_load_kv(
    unsigned base, int t,
    const __half* __restrict__ Kt, const __half* __restrict__ V,
    size_t bh, int k0)
{
    unsigned kS = base;
    unsigned vS = base + FK_BYTES;
#pragma unroll
    for (int i = 0; i < 4; i++) {
        int idx = t + i * 256;
        int kr = idx >> 3, kc = (idx & 7) * 8;
        size_t gk = bh + (size_t)kr * S_ + k0 + kc;
        cp16(kS + (unsigned)(kr * FK_STRIDE + kc) * 2u, Kt + gk);
        int vr = idx >> 4, vc = (idx & 15) * 8;
        size_t gv = bh + (size_t)(k0 + vr) * HS_ + vc;
        cp16(vS + (unsigned)(vr * FV_STRIDE + vc) * 2u, V + gv);
    }
}

__global__ __launch_bounds__(256) void flash_attn_mma(
    const __half* __restrict__ Q, const __half* __restrict__ Kt,
    const __half* __restrict__ V, const float* __restrict__ amask,
    __half* __restrict__ Out)
{
    extern __shared__ char dynsm[];
    const unsigned smb = smem_u32(dynsm);
    const unsigned sQ = smb;
    const unsigned sKV = smb + FQ_BYTES;

    const int t = threadIdx.x, lane = t & 31, w = t >> 5;
    const int qt = gridDim.x - 1 - blockIdx.x;
    const int q0 = qt * 128;
    const int h = blockIdx.y, b = blockIdx.z;
    const size_t bh = (size_t)(b * H_ + h) * S_ * HS_;

#pragma unroll
    for (int i = 0; i < 8; i++) {
        int idx = t + i * 256;
        int r = idx >> 4, c = (idx & 15) * 8;
        size_t g = bh + (size_t)(q0 + r) * HS_ + c;
        cp16(sQ + (unsigned)(r * FQ_STRIDE + c) * 2u, Q + g);
    }
    fa_load_kv(sKV, t, Kt, V, bh, 0);
    cp_commit();

    float Oa[16][4];
#pragma unroll
    for (int i = 0; i < 16; i++)
#pragma unroll
        for (int j = 0; j < 4; j++) Oa[i][j] = 0.f;

    float m0 = -1e30f, m1 = -1e30f, l0 = 0.f, l1 = 0.f;
    const int nkt = 2 * (qt + 1);
    const float scale = 0.08838834764831845f;
    const int qrow0 = q0 + w * 16 + (lane >> 2);
    const int col_t = 2 * (lane & 3);

    for (int kt = 0; kt < nkt; kt++) {
        const int k0 = kt * 64;
        const unsigned stg = sKV + (kt & 1) * FSTAGE;
        if (kt + 1 < nkt) {
            fa_load_kv(sKV + ((kt + 1) & 1) * FSTAGE, t, Kt, V, bh, (kt + 1) * 64);
            cp_commit();
            cp_wait_1();
        } else {
            cp_wait_0();
        }
        __syncthreads();

        float Sa[8][4];
#pragma unroll
        for (int i = 0; i < 8; i++)
#pragma unroll
            for (int j = 0; j < 4; j++) Sa[i][j] = 0.f;

#pragma unroll
        for (int kk = 0; kk < 8; kk++) {
            unsigned ah[4];
            unsigned qa = sQ + (unsigned)((w * 16 + (lane & 15)) * FQ_STRIDE
                                          + kk * 16 + ((lane >> 4) << 3)) * 2u;
            ldm4(ah, qa);
#pragma unroll
            for (int nb = 0; nb < 4; nb++) {
                unsigned kh[4];
                unsigned ka = stg + (unsigned)((kk * 16 + (lane & 15)) * FK_STRIDE
                                               + nb * 16 + ((lane >> 4) << 3)) * 2u;
                ldm4t(kh, ka);
#pragma unroll
                for (int hf = 0; hf < 2; hf++)
                    mma16816(Sa[nb * 2 + hf], ah, &kh[hf * 2]);
            }
        }

        const bool needmask = (k0 + 63 > q0 + w * 16);
        float mc0 = -1e30f, mc1 = -1e30f;
#pragma unroll
        for (int j = 0; j < 8; j++) {
            int cb = k0 + j * 8 + col_t;
            float a0 = amask[(size_t)b * S_ + cb];
            float a1 = amask[(size_t)b * S_ + cb + 1];
            Sa[j][0] = Sa[j][0] * scale + a0;
            Sa[j][1] = Sa[j][1] * scale + a1;
            Sa[j][2] = Sa[j][2] * scale + a0;
            Sa[j][3] = Sa[j][3] * scale + a1;
            if (needmask) {
                if (cb > qrow0)         Sa[j][0] = -1e30f;
                if (cb + 1 > qrow0)     Sa[j][1] = -1e30f;
                if (cb > qrow0 + 8)     Sa[j][2] = -1e30f;
                if (cb + 1 > qrow0 + 8) Sa[j][3] = -1e30f;
            }
            mc0 = fmaxf(mc0, fmaxf(Sa[j][0], Sa[j][1]));
            mc1 = fmaxf(mc1, fmaxf(Sa[j][2], Sa[j][3]));
        }
        mc0 = fmaxf(mc0, __shfl_xor_sync(0xffffffffu, mc0, 1));
        mc0 = fmaxf(mc0, __shfl_xor_sync(0xffffffffu, mc0, 2));
        mc1 = fmaxf(mc1, __shfl_xor_sync(0xffffffffu, mc1, 1));
        mc1 = fmaxf(mc1, __shfl_xor_sync(0xffffffffu, mc1, 2));

        float mn0 = fmaxf(m0, mc0), mn1 = fmaxf(m1, mc1);
        float sf0 = __expf(m0 - mn0), sf1 = __expf(m1 - mn1);
        m0 = mn0; m1 = mn1;

        float ps0 = 0.f, ps1 = 0.f;
        unsigned phi[4][4];
#pragma unroll
        for (int j = 0; j < 8; j++) {
            float p0 = __expf(Sa[j][0] - mn0);
            float p1 = __expf(Sa[j][1] - mn0);
            float p2 = __expf(Sa[j][2] - mn1);
            float p3 = __expf(Sa[j][3] - mn1);
            ps0 += p0 + p1;
            ps1 += p2 + p3;
            __half2 h01 = __floats2half2_rn(p0, p1);
            __half2 h23 = __floats2half2_rn(p2, p3);
            int kf = j >> 1, q = (j & 1) * 2;
            phi[kf][q + 0] = *reinterpret_cast<unsigned*>(&h01);
            phi[kf][q + 1] = *reinterpret_cast<unsigned*>(&h23);
        }
        ps0 += __shfl_xor_sync(0xffffffffu, ps0, 1);
        ps0 += __shfl_xor_sync(0xffffffffu, ps0, 2);
        ps1 += __shfl_xor_sync(0xffffffffu, ps1, 1);
        ps1 += __shfl_xor_sync(0xffffffffu, ps1, 2);
        l0 = l0 * sf0 + ps0;
        l1 = l1 * sf1 + ps1;

#pragma unroll
        for (int nb = 0; nb < 16; nb++) {
            Oa[nb][0] *= sf0; Oa[nb][1] *= sf0;
            Oa[nb][2] *= sf1; Oa[nb][3] *= sf1;
        }

        const unsigned vSb = stg + FK_BYTES;
#pragma unroll
        for (int kf = 0; kf < 4; kf++) {
#pragma unroll
            for (int nb = 0; nb < 8; nb++) {
                unsigned vh[4];
                unsigned va = vSb + (unsigned)((kf * 16 + (lane & 15)) * FV_STRIDE
                                               + nb * 16 + ((lane >> 4) << 3)) * 2u;
                ldm4t(vh, va);
#pragma unroll
                for (int hf = 0; hf < 2; hf++)
                    mma16816(Oa[nb * 2 + hf], phi[kf], &vh[hf * 2]);
            }
        }
        __syncthreads();
    }

    float rl0 = 1.0f / l0, rl1 = 1.0f / l1;
#pragma unroll
    for (int nb = 0; nb < 16; nb++) {
        int c = nb * 8 + col_t;
        __half2 h01 = __floats2half2_rn(Oa[nb][0] * rl0, Oa[nb][1] * rl0);
        __half2 h23 = __floats2half2_rn(Oa[nb][2] * rl1, Oa[nb][3] * rl1);
        size_t o0 = (size_t)(b * S_ + qrow0) * HID_ + h * HS_ + c;
        size_t o1 = o0 + (size_t)8 * HID_;
        *reinterpret_cast<__half2*>(Out + o0) = h01;
        *reinterpret_cast<__half2*>(Out + o1) = h23;
    }
}

// ---------------- launch ----------------
extern "C" void kernel_launch(void* const* d_in, const int* in_sizes, int n_in,
                              void* d_out, int out_size) {
    const float* hidden = (const float*)d_in[0];
    const float* amask  = (const float*)d_in[1];
    const int*   pos    = (const int*)d_in[2];
    const float* Wqkv   = (const float*)d_in[3];
    const float* bqkv   = (const float*)d_in[4];
    const float* Wd     = (const float*)d_in[5];
    const float* bd     = (const float*)d_in[6];
    float* out = (float*)d_out;

    __half *qkv, *A, *Wq, *Wdh, *Att, *Qp, *Kt, *Vp;
    cudaGetSymbolAddress((void**)&qkv, g_qkv);
    cudaGetSymbolAddress((void**)&A,   g_A);
    cudaGetSymbolAddress((void**)&Wq,  g_Wq);
    cudaGetSymbolAddress((void**)&Wdh, g_Wd);
    cudaGetSymbolAddress((void**)&Att, g_Att);
    cudaGetSymbolAddress((void**)&Qp,  g_Q);
    cudaGetSymbolAddress((void**)&Kt,  g_Kt);
    cudaGetSymbolAddress((void**)&Vp,  g_V);

    cudaFuncSetAttribute(gemm_big<1>, cudaFuncAttributeMaxDynamicSharedMemorySize, GEMM_SMEM);
    cudaFuncSetAttribute(gemm_big<0>, cudaFuncAttributeMaxDynamicSharedMemorySize, GEMM_SMEM);
    cudaFuncSetAttribute(rotary_split, cudaFuncAttributeMaxDynamicSharedMemorySize, ROT_SMEM);
    cudaFuncSetAttribute(flash_attn_mma, cudaFuncAttributeMaxDynamicSharedMemorySize, FA_SMEM);

    // 0) convert inputs/weights to fp16
    split1_fp16<<<(B_ * S_ * HID_ / 4 + 255) / 256, 256>>>(hidden, A, B_ * S_ * HID_ / 4);
    split1_fp16<<<(HID_ * 3 * HID_ / 4 + 255) / 256, 256>>>(Wqkv, Wq, HID_ * 3 * HID_ / 4);
    split1_fp16<<<(HID_ * HID_ / 4 + 255) / 256, 256>>>(Wd, Wdh, HID_ * HID_ / 4);

    // 1) QKV GEMM + bias -> fp16 qkv
    gemm_big<1><<<dim3((3 * HID_) / GBN, (B_ * S_) / GBM), 256, GEMM_SMEM>>>(
        A, Wq, bqkv, qkv, B_ * S_, 3 * HID_, HID_);

    // 2) rotary + K transpose (fp16 in/out)
    rotary_split<<<dim3(S_ / 128, H_, B_), 256, ROT_SMEM>>>(qkv, pos, Qp, Kt, Vp);

    // 3) tensor-core causal flash attention
    flash_attn_mma<<<dim3(S_ / 128, H_, B_), 256, FA_SMEM>>>(Qp, Kt, Vp, amask, Att);

    // 4) dense GEMM + bias -> fp32 out
    gemm_big<0><<<dim3(HID_ / GBN, (B_ * S_) / GBM), 256, GEMM_SMEM>>>(
        Att, Wdh, bd, out, B_ * S_, HID_, HID_);
}